// round 1
// baseline (speedup 1.0000x reference)
#include <cuda_runtime.h>
#include <cuda_bf16.h>
#include <cstdint>

// Quantized int8 3x3 VALID conv, groups=1.
// x: [64,16,256,256] int32 (int8 values), w: [16,16,3,3] int32, bias: [16] f32
// out: [64,16,254,254] f32
//
// out = 1e-4 * ( Sum x*w  - 3*Sum_window(x) - 7*Wsum[co] + 21*144 ) + bq[co]
// where bq = rint(bias/1e-4)*1e-4 (clamped).  Integer part is exact.

#define CIN 16
#define COUT 16
#define HIN 256
#define WIN 256
#define HOUT 254
#define WOUT 254
#define TH 16
#define TW 64
#define ROWS (TH + 2)   // 18
#define COLS (TW + 2)   // 66
#define PLANE (ROWS * COLS)          // 1188 words per cin-quad plane
#define XWORDS (4 * PLANE)           // 4752
#define NWW (COUT * 9 * 4)           // 576 packed weight words

__device__ unsigned int g_wpack[NWW];
__device__ int   g_wc[COUT];   // -7*Wsum + 3024
__device__ float g_bq[COUT];   // quantized-dequantized bias

__global__ void prep_kernel(const int* __restrict__ w, const float* __restrict__ bias) {
    int t = threadIdx.x;
    if (t < NWW) {
        int co = t / 36, rem = t % 36, p = rem >> 2, g = rem & 3;
        unsigned int pk = 0;
        #pragma unroll
        for (int j = 0; j < 4; j++) {
            int ci = 4 * g + j;
            int wv = w[(co * CIN + ci) * 9 + p];
            pk |= (unsigned int)(wv & 0xFF) << (8 * j);
        }
        g_wpack[(co * 9 + p) * 4 + g] = pk;
    }
    if (t < COUT) {
        int s = 0;
        #pragma unroll 4
        for (int k = 0; k < CIN * 9; k++) s += w[t * CIN * 9 + k];
        g_wc[t] = -7 * s + 21 * CIN * 9;
        float b = bias[t];
        float r = rintf(b / 0.0001f);                    // round half-to-even, matches jnp.round
        r = fminf(fmaxf(r, -2147483648.0f), 2147483647.0f);
        g_bq[t] = r * 0.0001f;
    }
}

__global__ void __launch_bounds__(256, 2)
conv_kernel(const int* __restrict__ inp, float* __restrict__ out) {
    __shared__ unsigned int sxm[XWORDS];   // [g][r][c], 4 int8 cins packed per word
    __shared__ unsigned int swm[NWW];      // [co][p][g]
    __shared__ int   swc[COUT];
    __shared__ float sbq[COUT];

    const int tid = threadIdx.x;
    const int n   = blockIdx.z;
    const int oh0 = blockIdx.y * TH;
    const int ow0 = blockIdx.x * TW;

    const int* xin = inp + (size_t)n * CIN * HIN * WIN;

    // ---- load + pack input tile ----
    for (int idx = tid; idx < XWORDS; idx += 256) {
        int g  = idx / PLANE;
        int rc = idx - g * PLANE;
        int r  = rc / COLS;
        int c  = rc - r * COLS;
        int ih = oh0 + r, iw = ow0 + c;
        unsigned int pk = 0;
        if (ih < HIN && iw < WIN) {
            const int* base = xin + (size_t)(4 * g) * HIN * WIN + ih * WIN + iw;
            int v0 = base[0];
            int v1 = base[HIN * WIN];
            int v2 = base[2 * HIN * WIN];
            int v3 = base[3 * HIN * WIN];
            pk = (unsigned int)(v0 & 0xFF) | ((unsigned int)(v1 & 0xFF) << 8) |
                 ((unsigned int)(v2 & 0xFF) << 16) | ((unsigned int)(v3 & 0xFF) << 24);
        }
        sxm[idx] = pk;
    }
    for (int idx = tid; idx < NWW; idx += 256) swm[idx] = g_wpack[idx];
    if (tid < COUT) { swc[tid] = g_wc[tid]; sbq[tid] = g_bq[tid]; }
    __syncthreads();

    // ---- per-thread: 4 adjacent output pixels on one row ----
    const int row = tid >> 4;      // 0..15
    const int cg  = tid & 15;      // 0..15 -> cols 4*cg .. 4*cg+3
    const int oh  = oh0 + row;
    const int ow  = ow0 + 4 * cg;

    // x window registers: [kh][g][c], c covers 6 columns
    unsigned int xv[3][4][6];
    #pragma unroll
    for (int kh = 0; kh < 3; kh++)
        #pragma unroll
        for (int g = 0; g < 4; g++) {
            const unsigned int* p = &sxm[g * PLANE + (row + kh) * COLS + 4 * cg];
            #pragma unroll
            for (int c = 0; c < 6; c++) xv[kh][g][c] = p[c];
        }

    // window sums (shared across all couts)
    int s0 = 0, s1 = 0, s2 = 0, s3 = 0;
    #pragma unroll
    for (int kh = 0; kh < 3; kh++)
        #pragma unroll
        for (int g = 0; g < 4; g++)
            #pragma unroll
            for (int kw = 0; kw < 3; kw++) {
                s0 = __dp4a((int)xv[kh][g][kw + 0], 0x01010101, s0);
                s1 = __dp4a((int)xv[kh][g][kw + 1], 0x01010101, s1);
                s2 = __dp4a((int)xv[kh][g][kw + 2], 0x01010101, s2);
                s3 = __dp4a((int)xv[kh][g][kw + 3], 0x01010101, s3);
            }

    const bool rowok = (oh < HOUT);
    float* ob = out + ((size_t)(n * COUT) * HOUT + oh) * WOUT + ow;

    #pragma unroll 1
    for (int co = 0; co < COUT; co++) {
        int a0 = 0, a1 = 0, a2 = 0, a3 = 0;
        const unsigned int* wp = &swm[co * 36];
        #pragma unroll
        for (int kh = 0; kh < 3; kh++)
            #pragma unroll
            for (int kw = 0; kw < 3; kw++)
                #pragma unroll
                for (int g = 0; g < 4; g++) {
                    int w = (int)wp[(kh * 3 + kw) * 4 + g];
                    a0 = __dp4a((int)xv[kh][g][kw + 0], w, a0);
                    a1 = __dp4a((int)xv[kh][g][kw + 1], w, a1);
                    a2 = __dp4a((int)xv[kh][g][kw + 2], w, a2);
                    a3 = __dp4a((int)xv[kh][g][kw + 3], w, a3);
                }
        if (rowok) {
            int wc = swc[co];
            float bq = sbq[co];
            float* o = ob + (size_t)co * HOUT * WOUT;
            if (ow + 0 < WOUT) o[0] = fmaf((float)(a0 - 3 * s0 + wc), 1e-4f, bq);
            if (ow + 1 < WOUT) o[1] = fmaf((float)(a1 - 3 * s1 + wc), 1e-4f, bq);
            if (ow + 2 < WOUT) o[2] = fmaf((float)(a2 - 3 * s2 + wc), 1e-4f, bq);
            if (ow + 3 < WOUT) o[3] = fmaf((float)(a3 - 3 * s3 + wc), 1e-4f, bq);
        }
    }
}

extern "C" void kernel_launch(void* const* d_in, const int* in_sizes, int n_in,
                              void* d_out, int out_size) {
    const int*   x    = (const int*)d_in[0];
    const int*   w    = (const int*)d_in[1];
    const float* bias = (const float*)d_in[2];
    float* out = (float*)d_out;

    prep_kernel<<<1, 576>>>(w, bias);

    dim3 grid((WOUT + TW - 1) / TW,   // 4
              (HOUT + TH - 1) / TH,   // 16
              64);                    // batch
    conv_kernel<<<grid, 256>>>(x, out);
}

// round 2
// speedup vs baseline: 1.5440x; 1.5440x over previous
#include <cuda_runtime.h>
#include <cuda_bf16.h>
#include <cstdint>

// Quantized int8 3x3 VALID conv, groups=1.
// x: [64,16,256,256] int32 (int8 values), w: [16,16,3,3] int32, bias: [16] f32
// out: [64,16,254,254] f32
//
// out = 1e-4 * ( Sum x*w - 3*Sum_window(x) - 7*Wsum[co] + 21*144 ) + bq[co]
// bq = rint(bias/1e-4)*1e-4 (clamped). Integer math is exact (dp4a).

#define CIN 16
#define COUT 16
#define HIN 256
#define WIN 256
#define HOUT 254
#define WOUT 254
#define TH 16
#define TW 64
#define ROWS (TH + 2)            // 18
#define COLS 68                  // 66 used + pad to 16B multiple
#define PLANE (ROWS * COLS)      // 1224
#define XWORDS (4 * PLANE)       // 4896
#define NWW (COUT * 9 * 4)       // 576 packed weight words
#define G4_PER_ROW 17            // 68/4 int4 groups per row
#define NGROUPS (4 * ROWS * G4_PER_ROW)  // 1224

__device__ __align__(16) unsigned int g_wpack[NWW];  // [co][p][g]
__device__ int   g_wc[COUT];   // -7*Wsum + 21*144
__device__ float g_bq[COUT];   // quantize-dequantized bias

__global__ void prep_kernel(const int* __restrict__ w, const float* __restrict__ bias) {
    int t = threadIdx.x;
    if (t < NWW) {
        int co = t / 36, rem = t % 36, p = rem >> 2, g = rem & 3;
        unsigned int pk = 0;
        #pragma unroll
        for (int j = 0; j < 4; j++) {
            int wv = w[(co * CIN + (4 * g + j)) * 9 + p];
            pk |= (unsigned int)(wv & 0xFF) << (8 * j);
        }
        g_wpack[(co * 9 + p) * 4 + g] = pk;
    }
    if (t < COUT) {
        int s = 0;
        #pragma unroll 4
        for (int k = 0; k < CIN * 9; k++) s += w[t * CIN * 9 + k];
        g_wc[t] = -7 * s + 21 * CIN * 9;
        float b = bias[t];
        float r = rintf(b / 0.0001f);
        r = fminf(fmaxf(r, -2147483648.0f), 2147483647.0f);
        g_bq[t] = r * 0.0001f;
    }
}

__device__ __forceinline__ unsigned pack4(int a, int b, int c, int d) {
    unsigned t = __byte_perm((unsigned)a, (unsigned)b, 0x0040);
    unsigned u = __byte_perm((unsigned)c, (unsigned)d, 0x4000);
    return __byte_perm(t, u, 0x7610);
}

__global__ void __launch_bounds__(256, 2)
conv_kernel(const int* __restrict__ inp, float* __restrict__ out) {
    __shared__ __align__(16) unsigned int sxm[XWORDS];  // [g][r][c]
    __shared__ __align__(16) uint4 swv[COUT * 9];        // [co][p], .x..w = g0..g3
    __shared__ int   swc[COUT];
    __shared__ float sbq[COUT];

    const int tid = threadIdx.x;
    const int n   = blockIdx.z;
    const int oh0 = blockIdx.y * TH;
    const int ow0 = blockIdx.x * TW;

    const int* xin = inp + (size_t)n * CIN * HIN * WIN;

    // ---- load + pack input tile (vectorized, PRMT byte-transpose) ----
    for (int gi = tid; gi < NGROUPS; gi += 256) {
        int g   = gi / (ROWS * G4_PER_ROW);
        int rem = gi - g * (ROWS * G4_PER_ROW);
        int r   = rem / G4_PER_ROW;
        int c4  = (rem - r * G4_PER_ROW) * 4;
        int ih = oh0 + r, iw = ow0 + c4;
        uint4 pk;
        const int* base = xin + (size_t)(4 * g) * (HIN * WIN) + ih * WIN + iw;
        if (ih < HIN && iw + 3 < WIN) {
            int4 v0 = *(const int4*)(base);
            int4 v1 = *(const int4*)(base + HIN * WIN);
            int4 v2 = *(const int4*)(base + 2 * HIN * WIN);
            int4 v3 = *(const int4*)(base + 3 * HIN * WIN);
            pk.x = pack4(v0.x, v1.x, v2.x, v3.x);
            pk.y = pack4(v0.y, v1.y, v2.y, v3.y);
            pk.z = pack4(v0.z, v1.z, v2.z, v3.z);
            pk.w = pack4(v0.w, v1.w, v2.w, v3.w);
        } else {
            unsigned t[4];
            #pragma unroll
            for (int j = 0; j < 4; j++) {
                t[j] = 0;
                if (ih < HIN && iw + j < WIN) {
                    int v0 = base[j];
                    int v1 = base[j + HIN * WIN];
                    int v2 = base[j + 2 * HIN * WIN];
                    int v3 = base[j + 3 * HIN * WIN];
                    t[j] = pack4(v0, v1, v2, v3);
                }
            }
            pk.x = t[0]; pk.y = t[1]; pk.z = t[2]; pk.w = t[3];
        }
        *(uint4*)&sxm[g * PLANE + r * COLS + c4] = pk;
    }
    {
        const uint4* wsrc = (const uint4*)g_wpack;
        for (int idx = tid; idx < COUT * 9; idx += 256) swv[idx] = wsrc[idx];
        if (tid < COUT) { swc[tid] = g_wc[tid]; sbq[tid] = g_bq[tid]; }
    }
    __syncthreads();

    // ---- per-thread: 4 adjacent output pixels on one row ----
    const int row = tid >> 4;      // 0..15
    const int cg  = tid & 15;      // cols 4*cg .. 4*cg+3
    const int oh  = oh0 + row;
    const int ow  = ow0 + 4 * cg;

    // x window registers: [kh][g][c], 6 cols (vectorized loads)
    unsigned int xv[3][4][6];
    #pragma unroll
    for (int kh = 0; kh < 3; kh++)
        #pragma unroll
        for (int g = 0; g < 4; g++) {
            const unsigned int* p = &sxm[g * PLANE + (row + kh) * COLS + 4 * cg];
            uint4 q0 = *(const uint4*)p;
            uint2 q1 = *(const uint2*)(p + 4);
            xv[kh][g][0] = q0.x; xv[kh][g][1] = q0.y; xv[kh][g][2] = q0.z;
            xv[kh][g][3] = q0.w; xv[kh][g][4] = q1.x; xv[kh][g][5] = q1.y;
        }

    // window sums (shared across all couts)
    int s[4] = {0, 0, 0, 0};
    #pragma unroll
    for (int kh = 0; kh < 3; kh++)
        #pragma unroll
        for (int g = 0; g < 4; g++)
            #pragma unroll
            for (int kw = 0; kw < 3; kw++)
                #pragma unroll
                for (int p = 0; p < 4; p++)
                    s[p] = __dp4a((int)xv[kh][g][kw + p], 0x01010101, s[p]);

    const bool rowok = (oh < HOUT);
    float* ob = out + ((size_t)(n * COUT) * HOUT + oh) * WOUT + ow;

    #pragma unroll 1
    for (int co = 0; co < COUT; co += 2) {
        int a0[4] = {0, 0, 0, 0};
        int a1[4] = {0, 0, 0, 0};
        const uint4* wpA = &swv[co * 9];
        const uint4* wpB = wpA + 9;
        #pragma unroll
        for (int kh = 0; kh < 3; kh++)
            #pragma unroll
            for (int kw = 0; kw < 3; kw++) {
                uint4 wA = wpA[kh * 3 + kw];
                uint4 wB = wpB[kh * 3 + kw];
                #pragma unroll
                for (int p = 0; p < 4; p++) {
                    a0[p] = __dp4a((int)xv[kh][0][kw + p], (int)wA.x, a0[p]);
                    a0[p] = __dp4a((int)xv[kh][1][kw + p], (int)wA.y, a0[p]);
                    a0[p] = __dp4a((int)xv[kh][2][kw + p], (int)wA.z, a0[p]);
                    a0[p] = __dp4a((int)xv[kh][3][kw + p], (int)wA.w, a0[p]);
                    a1[p] = __dp4a((int)xv[kh][0][kw + p], (int)wB.x, a1[p]);
                    a1[p] = __dp4a((int)xv[kh][1][kw + p], (int)wB.y, a1[p]);
                    a1[p] = __dp4a((int)xv[kh][2][kw + p], (int)wB.z, a1[p]);
                    a1[p] = __dp4a((int)xv[kh][3][kw + p], (int)wB.w, a1[p]);
                }
            }
        if (rowok) {
            int   wc0 = swc[co],     wc1 = swc[co + 1];
            float bq0 = sbq[co],     bq1 = sbq[co + 1];
            float* o0 = ob + (size_t)co * HOUT * WOUT;
            float* o1 = o0 + (size_t)HOUT * WOUT;
            #pragma unroll
            for (int p = 0; p < 4; p++) {
                if (ow + p < WOUT) {
                    o0[p] = fmaf((float)(a0[p] - 3 * s[p] + wc0), 1e-4f, bq0);
                    o1[p] = fmaf((float)(a1[p] - 3 * s[p] + wc1), 1e-4f, bq1);
                }
            }
        }
    }
}

extern "C" void kernel_launch(void* const* d_in, const int* in_sizes, int n_in,
                              void* d_out, int out_size) {
    const int*   x    = (const int*)d_in[0];
    const int*   w    = (const int*)d_in[1];
    const float* bias = (const float*)d_in[2];
    float* out = (float*)d_out;

    prep_kernel<<<1, 576>>>(w, bias);

    dim3 grid((WOUT + TW - 1) / TW,   // 4
              (HOUT + TH - 1) / TH,   // 16
              64);                    // batch
    conv_kernel<<<grid, 256>>>(x, out);
}